// round 13
// baseline (speedup 1.0000x reference)
#include <cuda_runtime.h>
#include <cstdint>

#define BB 4
#define HH 1024
#define WW 1920
#define HW (HH * WW)
#define NPIX (BB * HW)
#define ALPHA 100.0f
#define EPSN 1e-7f

#define TW 128   // tile width  (1920 = 15*128)
#define TH 32    // tile height (1024 = 32*32)
#define TY 8     // block y-threads; TH/TY = 4 rows per thread

// Interleaved accumulator: [pix][4] = {num_r, num_g, num_b, den}, 16B aligned.
// Zero-initialized at module load; norm_kernel re-zeroes it every call, so
// every graph replay starts from zeros (no memset node needed).
__device__ __align__(16) float g_acc[(size_t)NPIX * 4];

__device__ __forceinline__ void red_add_v4(float* addr, float a, float b, float c, float d) {
    asm volatile("red.global.add.v4.f32 [%0], {%1, %2, %3, %4};"
                 :: "l"(addr), "f"(a), "f"(b), "f"(c), "f"(d) : "memory");
}

__global__ __launch_bounds__(1024, 2)
void splat_kernel(const float* __restrict__ rgb1,
                  const float* __restrict__ rgb2,
                  const float* __restrict__ ftgt,
                  const float* __restrict__ f12,
                  float* __restrict__ out) {
    int b     = blockIdx.z;
    int x     = blockIdx.x * TW + threadIdx.x;
    int ybase = blockIdx.y * TH + threadIdx.y;

    const float* r2   = rgb2 + (size_t)b * 3 * HW;
    const float* r1b  = rgb1 + (size_t)b * 3 * HW;
    const float* flb  = f12  + (size_t)b * 2 * HW;
    const float* ftb  = ftgt + (size_t)b * 2 * HW;
    float*       accb = g_acc + (size_t)b * HW * 4;
    float*       metb = out + (size_t)BB * 3 * HW + (size_t)b * HW;

#pragma unroll
    for (int i = 0; i < TH / TY; i++) {
        int y   = ybase + i * TY;
        int rem = y * WW + x;

        // ---- backwarp src2 with flow_src1_to_src2 (bilinear gather, zero outside) ----
        float px = (float)x + flb[rem];
        float py = (float)y + flb[rem + HW];
        float x0f = floorf(px), y0f = floorf(py);
        int   x0  = (int)x0f,   y0  = (int)y0f;
        float wx = px - x0f, wy = py - y0f;

        float a0 = 0.f, a1 = 0.f, a2 = 0.f;
#pragma unroll
        for (int cy = 0; cy < 2; cy++) {
#pragma unroll
            for (int cx = 0; cx < 2; cx++) {
                int xi = x0 + cx, yi = y0 + cy;
                if (xi >= 0 && xi < WW && yi >= 0 && yi < HH) {
                    float w = (cx ? wx : 1.f - wx) * (cy ? wy : 1.f - wy);
                    int o = yi * WW + xi;
                    a0 += w * __ldg(r2 + o);
                    a1 += w * __ldg(r2 + o + HW);
                    a2 += w * __ldg(r2 + o + 2 * HW);
                }
            }
        }

        float c0 = r1b[rem], c1 = r1b[rem + HW], c2 = r1b[rem + 2 * HW];

        float metric = (fabsf(c0 - a0) + fabsf(c1 - a1) + fabsf(c2 - a2)) * (1.f / 3.f);
        metb[rem] = metric;

        float m  = fmaxf(-ALPHA * metric, -ALPHA);  // upper clip can't trigger (metric>=0)
        float em = expf(m);

        // ---- forward splat with flow_src1_to_tgt (bilinear scatter-add) ----
        px = (float)x + ftb[rem];
        py = (float)y + ftb[rem + HW];
        x0f = floorf(px); y0f = floorf(py);
        x0 = (int)x0f; y0 = (int)y0f;
        wx = px - x0f; wy = py - y0f;

        float v0 = c0 * em, v1 = c1 * em, v2 = c2 * em;
#pragma unroll
        for (int cy = 0; cy < 2; cy++) {
#pragma unroll
            for (int cx = 0; cx < 2; cx++) {
                int xi = x0 + cx, yi = y0 + cy;
                if (xi >= 0 && xi < WW && yi >= 0 && yi < HH) {
                    float w = (cx ? wx : 1.f - wx) * (cy ? wy : 1.f - wy);
                    float* p = accb + (size_t)(yi * WW + xi) * 4;
                    red_add_v4(p, v0 * w, v1 * w, v2 * w, em * w);
                }
            }
        }
    }
}

// ---- Normalize + re-zero accumulator (replaces the memset node) ----
__global__ __launch_bounds__(256)
void norm_kernel(float* __restrict__ out) {
    int idx = blockIdx.x * blockDim.x + threadIdx.x;
    if (idx >= NPIX) return;
    int b   = idx / HW;
    int rem = idx - b * HW;
    float4* ap = reinterpret_cast<float4*>(g_acc + (size_t)idx * 4);
    float4 acc = *ap;
    *ap = make_float4(0.f, 0.f, 0.f, 0.f);
    float inv = 1.0f / (acc.w + EPSN);
    float* o = out + (size_t)b * 3 * HW + rem;
    o[0]      = acc.x * inv;
    o[HW]     = acc.y * inv;
    o[2 * HW] = acc.z * inv;
}

// Tail node: shifts ncu's "-s 5" sample onto the main splat_kernel.
__global__ void tail_kernel() {}

extern "C" void kernel_launch(void* const* d_in, const int* in_sizes, int n_in,
                              void* d_out, int out_size) {
    const float* rgb1 = (const float*)d_in[0];
    const float* rgb2 = (const float*)d_in[1];
    const float* ftgt = (const float*)d_in[2];  // flow_src1_to_tgt
    const float* f12  = (const float*)d_in[3];  // flow_src1_to_src2
    float* out = (float*)d_out;

    dim3 block(TW, TY, 1);                        // 128 x 8 = 1024 threads
    dim3 grid(WW / TW, HH / TH, BB);              // 15 x 32 x 4 = 1920 CTAs
    splat_kernel<<<grid, block>>>(rgb1, rgb2, ftgt, f12, out);

    int threads = 256;
    int blocks  = (NPIX + threads - 1) / threads;
    norm_kernel<<<blocks, threads>>>(out);

    tail_kernel<<<1, 32>>>();
}

// round 14
// speedup vs baseline: 1.5539x; 1.5539x over previous
#include <cuda_runtime.h>
#include <cstdint>

#define BB 4
#define HH 1024
#define WW 1920
#define HW (HH * WW)
#define NPIX (BB * HW)
#define ALPHA 100.0f
#define EPSN 1e-7f

#define TW 128   // tile width  (1920 = 15*128)
#define TH 64    // tile height (1024 = 16*64)
#define TY 8     // block y-threads; TH/TY = 8 rows per thread

// Interleaved accumulator: [pix][4] = {num_r, num_g, num_b, den}, 16B aligned.
__device__ __align__(16) float g_acc[(size_t)NPIX * 4];

__device__ __forceinline__ void red_add_v4(float* addr, float a, float b, float c, float d) {
    asm volatile("red.global.add.v4.f32 [%0], {%1, %2, %3, %4};"
                 :: "l"(addr), "f"(a), "f"(b), "f"(c), "f"(d) : "memory");
}

__global__ __launch_bounds__(1024, 2)
void splat_kernel(const float* __restrict__ rgb1,
                  const float* __restrict__ rgb2,
                  const float* __restrict__ ftgt,
                  const float* __restrict__ f12,
                  float* __restrict__ out) {
    int b     = blockIdx.z;
    int x     = blockIdx.x * TW + threadIdx.x;
    int ybase = blockIdx.y * TH + threadIdx.y;

    const float* r2   = rgb2 + (size_t)b * 3 * HW;
    const float* r1b  = rgb1 + (size_t)b * 3 * HW;
    const float* flb  = f12  + (size_t)b * 2 * HW;
    const float* ftb  = ftgt + (size_t)b * 2 * HW;
    float*       accb = g_acc + (size_t)b * HW * 4;
    float*       metb = out + (size_t)BB * 3 * HW + (size_t)b * HW;

#pragma unroll
    for (int i = 0; i < TH / TY; i++) {
        int y   = ybase + i * TY;
        int rem = y * WW + x;

        // ---- backwarp src2 with flow_src1_to_src2 (bilinear gather, zero outside) ----
        float px = (float)x + flb[rem];
        float py = (float)y + flb[rem + HW];
        float x0f = floorf(px), y0f = floorf(py);
        int   x0  = (int)x0f,   y0  = (int)y0f;
        float wx = px - x0f, wy = py - y0f;

        float a0 = 0.f, a1 = 0.f, a2 = 0.f;
#pragma unroll
        for (int cy = 0; cy < 2; cy++) {
#pragma unroll
            for (int cx = 0; cx < 2; cx++) {
                int xi = x0 + cx, yi = y0 + cy;
                if (xi >= 0 && xi < WW && yi >= 0 && yi < HH) {
                    float w = (cx ? wx : 1.f - wx) * (cy ? wy : 1.f - wy);
                    int o = yi * WW + xi;
                    a0 += w * __ldg(r2 + o);
                    a1 += w * __ldg(r2 + o + HW);
                    a2 += w * __ldg(r2 + o + 2 * HW);
                }
            }
        }

        float c0 = r1b[rem], c1 = r1b[rem + HW], c2 = r1b[rem + 2 * HW];

        float metric = (fabsf(c0 - a0) + fabsf(c1 - a1) + fabsf(c2 - a2)) * (1.f / 3.f);
        metb[rem] = metric;

        float m  = fmaxf(-ALPHA * metric, -ALPHA);  // upper clip can't trigger (metric>=0)
        float em = expf(m);

        // ---- forward splat with flow_src1_to_tgt (bilinear scatter-add) ----
        px = (float)x + ftb[rem];
        py = (float)y + ftb[rem + HW];
        x0f = floorf(px); y0f = floorf(py);
        x0 = (int)x0f; y0 = (int)y0f;
        wx = px - x0f; wy = py - y0f;

        float v0 = c0 * em, v1 = c1 * em, v2 = c2 * em;
#pragma unroll
        for (int cy = 0; cy < 2; cy++) {
#pragma unroll
            for (int cx = 0; cx < 2; cx++) {
                int xi = x0 + cx, yi = y0 + cy;
                if (xi >= 0 && xi < WW && yi >= 0 && yi < HH) {
                    float w = (cx ? wx : 1.f - wx) * (cy ? wy : 1.f - wy);
                    float* p = accb + (size_t)(yi * WW + xi) * 4;
                    red_add_v4(p, v0 * w, v1 * w, v2 * w, em * w);
                }
            }
        }
    }
}

// ---- Normalize (memset node handles zeroing — fold experiment reverted) ----
__global__ __launch_bounds__(256)
void norm_kernel(float* __restrict__ out) {
    int idx = blockIdx.x * blockDim.x + threadIdx.x;
    if (idx >= NPIX) return;
    int b   = idx / HW;
    int rem = idx - b * HW;
    float4 acc = *reinterpret_cast<const float4*>(g_acc + (size_t)idx * 4);
    float inv = 1.0f / (acc.w + EPSN);
    float* o = out + (size_t)b * 3 * HW + rem;
    o[0]      = acc.x * inv;
    o[HW]     = acc.y * inv;
    o[2 * HW] = acc.z * inv;
}

// Tail node: keeps ncu's "-s 5" sample on the main splat_kernel.
__global__ void tail_kernel() {}

extern "C" void kernel_launch(void* const* d_in, const int* in_sizes, int n_in,
                              void* d_out, int out_size) {
    const float* rgb1 = (const float*)d_in[0];
    const float* rgb2 = (const float*)d_in[1];
    const float* ftgt = (const float*)d_in[2];  // flow_src1_to_tgt
    const float* f12  = (const float*)d_in[3];  // flow_src1_to_src2
    float* out = (float*)d_out;

    void* accp = nullptr;
    cudaGetSymbolAddress(&accp, g_acc);
    cudaMemsetAsync(accp, 0, (size_t)NPIX * 4 * sizeof(float));

    dim3 block(TW, TY, 1);                        // 128 x 8 = 1024 threads
    dim3 grid(WW / TW, HH / TH, BB);              // 15 x 16 x 4 = 960 CTAs
    splat_kernel<<<grid, block>>>(rgb1, rgb2, ftgt, f12, out);

    int threads = 256;
    int blocks  = (NPIX + threads - 1) / threads;
    norm_kernel<<<blocks, threads>>>(out);

    tail_kernel<<<1, 32>>>();
}

// round 15
// speedup vs baseline: 1.7350x; 1.1165x over previous
#include <cuda_runtime.h>
#include <cstdint>

#define BB 4
#define HH 1024
#define WW 1920
#define HW (HH * WW)
#define NPIX (BB * HW)
#define ALPHA 100.0f
#define EPSN 1e-7f

#define TW 64    // tile width  (1920 = 30*64)
#define TH 64    // tile height (1024 = 16*64)
#define TY 16    // block y-threads; TH/TY = 4 rows per thread (1024 threads)

// Interleaved accumulator: [pix][4] = {num_r, num_g, num_b, den}, 16B aligned.
__device__ __align__(16) float g_acc[(size_t)NPIX * 4];

__device__ __forceinline__ void red_add_v4(float* addr, float a, float b, float c, float d) {
    asm volatile("red.global.add.v4.f32 [%0], {%1, %2, %3, %4};"
                 :: "l"(addr), "f"(a), "f"(b), "f"(c), "f"(d) : "memory");
}

__global__ __launch_bounds__(1024, 2)
void splat_kernel(const float* __restrict__ rgb1,
                  const float* __restrict__ rgb2,
                  const float* __restrict__ ftgt,
                  const float* __restrict__ f12,
                  float* __restrict__ out) {
    int b     = blockIdx.z;
    int x     = blockIdx.x * TW + threadIdx.x;
    int ybase = blockIdx.y * TH + threadIdx.y;

    const float* r2   = rgb2 + (size_t)b * 3 * HW;
    const float* r1b  = rgb1 + (size_t)b * 3 * HW;
    const float* flb  = f12  + (size_t)b * 2 * HW;
    const float* ftb  = ftgt + (size_t)b * 2 * HW;
    float*       accb = g_acc + (size_t)b * HW * 4;
    float*       metb = out + (size_t)BB * 3 * HW + (size_t)b * HW;

#pragma unroll
    for (int i = 0; i < TH / TY; i++) {
        int y   = ybase + i * TY;
        int rem = y * WW + x;

        // ---- backwarp src2 with flow_src1_to_src2 (bilinear gather, zero outside) ----
        float px = (float)x + flb[rem];
        float py = (float)y + flb[rem + HW];
        float x0f = floorf(px), y0f = floorf(py);
        int   x0  = (int)x0f,   y0  = (int)y0f;
        float wx = px - x0f, wy = py - y0f;

        float a0 = 0.f, a1 = 0.f, a2 = 0.f;
#pragma unroll
        for (int cy = 0; cy < 2; cy++) {
#pragma unroll
            for (int cx = 0; cx < 2; cx++) {
                int xi = x0 + cx, yi = y0 + cy;
                if (xi >= 0 && xi < WW && yi >= 0 && yi < HH) {
                    float w = (cx ? wx : 1.f - wx) * (cy ? wy : 1.f - wy);
                    int o = yi * WW + xi;
                    a0 += w * __ldg(r2 + o);
                    a1 += w * __ldg(r2 + o + HW);
                    a2 += w * __ldg(r2 + o + 2 * HW);
                }
            }
        }

        float c0 = r1b[rem], c1 = r1b[rem + HW], c2 = r1b[rem + 2 * HW];

        float metric = (fabsf(c0 - a0) + fabsf(c1 - a1) + fabsf(c2 - a2)) * (1.f / 3.f);
        metb[rem] = metric;

        float m  = fmaxf(-ALPHA * metric, -ALPHA);  // upper clip can't trigger (metric>=0)
        float em = expf(m);

        // ---- forward splat with flow_src1_to_tgt (bilinear scatter-add) ----
        px = (float)x + ftb[rem];
        py = (float)y + ftb[rem + HW];
        x0f = floorf(px); y0f = floorf(py);
        x0 = (int)x0f; y0 = (int)y0f;
        wx = px - x0f; wy = py - y0f;

        float v0 = c0 * em, v1 = c1 * em, v2 = c2 * em;
#pragma unroll
        for (int cy = 0; cy < 2; cy++) {
#pragma unroll
            for (int cx = 0; cx < 2; cx++) {
                int xi = x0 + cx, yi = y0 + cy;
                if (xi >= 0 && xi < WW && yi >= 0 && yi < HH) {
                    float w = (cx ? wx : 1.f - wx) * (cy ? wy : 1.f - wy);
                    float* p = accb + (size_t)(yi * WW + xi) * 4;
                    red_add_v4(p, v0 * w, v1 * w, v2 * w, em * w);
                }
            }
        }
    }
}

// ---- Normalize (memset node handles zeroing) ----
__global__ __launch_bounds__(256)
void norm_kernel(float* __restrict__ out) {
    int idx = blockIdx.x * blockDim.x + threadIdx.x;
    if (idx >= NPIX) return;
    int b   = idx / HW;
    int rem = idx - b * HW;
    float4 acc = *reinterpret_cast<const float4*>(g_acc + (size_t)idx * 4);
    float inv = 1.0f / (acc.w + EPSN);
    float* o = out + (size_t)b * 3 * HW + rem;
    o[0]      = acc.x * inv;
    o[HW]     = acc.y * inv;
    o[2 * HW] = acc.z * inv;
}

// Tail node: keeps ncu's "-s 5" sample on the main splat_kernel.
__global__ void tail_kernel() {}

extern "C" void kernel_launch(void* const* d_in, const int* in_sizes, int n_in,
                              void* d_out, int out_size) {
    const float* rgb1 = (const float*)d_in[0];
    const float* rgb2 = (const float*)d_in[1];
    const float* ftgt = (const float*)d_in[2];  // flow_src1_to_tgt
    const float* f12  = (const float*)d_in[3];  // flow_src1_to_src2
    float* out = (float*)d_out;

    void* accp = nullptr;
    cudaGetSymbolAddress(&accp, g_acc);
    cudaMemsetAsync(accp, 0, (size_t)NPIX * 4 * sizeof(float));

    dim3 block(TW, TY, 1);                        // 64 x 16 = 1024 threads
    dim3 grid(WW / TW, HH / TH, BB);              // 30 x 16 x 4 = 1920 CTAs
    splat_kernel<<<grid, block>>>(rgb1, rgb2, ftgt, f12, out);

    int threads = 256;
    int blocks  = (NPIX + threads - 1) / threads;
    norm_kernel<<<blocks, threads>>>(out);

    tail_kernel<<<1, 32>>>();
}

// round 16
// speedup vs baseline: 1.8033x; 1.0393x over previous
#include <cuda_runtime.h>
#include <cstdint>

#define BB 4
#define HH 1024
#define WW 1920
#define HW (HH * WW)
#define NPIX (BB * HW)
#define ALPHA 100.0f
#define EPSN 1e-7f

#define TW 128   // tile width  (1920 = 15*128)
#define TH 32    // tile height (1024 = 32*32)
#define TY 4     // block y-threads; TH/TY = 8 rows per thread (512 threads)

// Interleaved accumulator: [pix][4] = {num_r, num_g, num_b, den}, 16B aligned.
__device__ __align__(16) float g_acc[(size_t)NPIX * 4];

__device__ __forceinline__ void red_add_v4(float* addr, float a, float b, float c, float d) {
    asm volatile("red.global.add.v4.f32 [%0], {%1, %2, %3, %4};"
                 :: "l"(addr), "f"(a), "f"(b), "f"(c), "f"(d) : "memory");
}

__global__ __launch_bounds__(512, 2)   // 64 regs/thread: room for front-batched MLP
void splat_kernel(const float* __restrict__ rgb1,
                  const float* __restrict__ rgb2,
                  const float* __restrict__ ftgt,
                  const float* __restrict__ f12,
                  float* __restrict__ out) {
    int b     = blockIdx.z;
    int x     = blockIdx.x * TW + threadIdx.x;
    int ybase = blockIdx.y * TH + threadIdx.y;

    const float* r2   = rgb2 + (size_t)b * 3 * HW;
    const float* r1b  = rgb1 + (size_t)b * 3 * HW;
    const float* flb  = f12  + (size_t)b * 2 * HW;
    const float* ftb  = ftgt + (size_t)b * 2 * HW;
    float*       accb = g_acc + (size_t)b * HW * 4;
    float*       metb = out + (size_t)BB * 3 * HW + (size_t)b * HW;

#pragma unroll
    for (int i = 0; i < TH / TY; i++) {
        int y   = ybase + i * TY;
        int rem = y * WW + x;

        // ---- backwarp src2 with flow_src1_to_src2 (bilinear gather, zero outside) ----
        float px = (float)x + flb[rem];
        float py = (float)y + flb[rem + HW];
        float x0f = floorf(px), y0f = floorf(py);
        int   x0  = (int)x0f,   y0  = (int)y0f;
        float wx = px - x0f, wy = py - y0f;

        float a0 = 0.f, a1 = 0.f, a2 = 0.f;
#pragma unroll
        for (int cy = 0; cy < 2; cy++) {
#pragma unroll
            for (int cx = 0; cx < 2; cx++) {
                int xi = x0 + cx, yi = y0 + cy;
                if (xi >= 0 && xi < WW && yi >= 0 && yi < HH) {
                    float w = (cx ? wx : 1.f - wx) * (cy ? wy : 1.f - wy);
                    int o = yi * WW + xi;
                    a0 += w * __ldg(r2 + o);
                    a1 += w * __ldg(r2 + o + HW);
                    a2 += w * __ldg(r2 + o + 2 * HW);
                }
            }
        }

        float c0 = r1b[rem], c1 = r1b[rem + HW], c2 = r1b[rem + 2 * HW];

        float metric = (fabsf(c0 - a0) + fabsf(c1 - a1) + fabsf(c2 - a2)) * (1.f / 3.f);
        metb[rem] = metric;

        float m  = fmaxf(-ALPHA * metric, -ALPHA);  // upper clip can't trigger (metric>=0)
        float em = expf(m);

        // ---- forward splat with flow_src1_to_tgt (bilinear scatter-add) ----
        px = (float)x + ftb[rem];
        py = (float)y + ftb[rem + HW];
        x0f = floorf(px); y0f = floorf(py);
        x0 = (int)x0f; y0 = (int)y0f;
        wx = px - x0f; wy = py - y0f;

        float v0 = c0 * em, v1 = c1 * em, v2 = c2 * em;
#pragma unroll
        for (int cy = 0; cy < 2; cy++) {
#pragma unroll
            for (int cx = 0; cx < 2; cx++) {
                int xi = x0 + cx, yi = y0 + cy;
                if (xi >= 0 && xi < WW && yi >= 0 && yi < HH) {
                    float w = (cx ? wx : 1.f - wx) * (cy ? wy : 1.f - wy);
                    float* p = accb + (size_t)(yi * WW + xi) * 4;
                    red_add_v4(p, v0 * w, v1 * w, v2 * w, em * w);
                }
            }
        }
    }
}

// ---- Normalize (memset node handles zeroing) ----
__global__ __launch_bounds__(256)
void norm_kernel(float* __restrict__ out) {
    int idx = blockIdx.x * blockDim.x + threadIdx.x;
    if (idx >= NPIX) return;
    int b   = idx / HW;
    int rem = idx - b * HW;
    float4 acc = *reinterpret_cast<const float4*>(g_acc + (size_t)idx * 4);
    float inv = 1.0f / (acc.w + EPSN);
    float* o = out + (size_t)b * 3 * HW + rem;
    o[0]      = acc.x * inv;
    o[HW]     = acc.y * inv;
    o[2 * HW] = acc.z * inv;
}

// Tail node: keeps ncu's "-s 5" sample on the main splat_kernel.
__global__ void tail_kernel() {}

extern "C" void kernel_launch(void* const* d_in, const int* in_sizes, int n_in,
                              void* d_out, int out_size) {
    const float* rgb1 = (const float*)d_in[0];
    const float* rgb2 = (const float*)d_in[1];
    const float* ftgt = (const float*)d_in[2];  // flow_src1_to_tgt
    const float* f12  = (const float*)d_in[3];  // flow_src1_to_src2
    float* out = (float*)d_out;

    void* accp = nullptr;
    cudaGetSymbolAddress(&accp, g_acc);
    cudaMemsetAsync(accp, 0, (size_t)NPIX * 4 * sizeof(float));

    dim3 block(TW, TY, 1);                        // 128 x 4 = 512 threads
    dim3 grid(WW / TW, HH / TH, BB);              // 15 x 32 x 4 = 1920 CTAs
    splat_kernel<<<grid, block>>>(rgb1, rgb2, ftgt, f12, out);

    int threads = 256;
    int blocks  = (NPIX + threads - 1) / threads;
    norm_kernel<<<blocks, threads>>>(out);

    tail_kernel<<<1, 32>>>();
}